// round 1
// baseline (speedup 1.0000x reference)
#include <cuda_runtime.h>
#include <math.h>

// ---------------------------------------------------------------------------
// MMFConv2d: per-pixel channel-LN + int8 fake-quant, ternary weight quant,
// 3x3 conv stride1 pad1, bias add.
// B=8, C=64, H=W=256, Cout=64, k=3.
// Round 1: fp32 baseline. Norm kernel (HBM-bound) + smem-tiled direct conv
// (FMA-bound).
// ---------------------------------------------------------------------------

#define B_ 8
#define C_ 64
#define H_ 256
#define W_ 256
#define HW_ (H_ * W_)
#define BHW_ (B_ * HW_)

// scratch: quantized activations, NCHW, same layout as input
__device__ float g_y[(size_t)B_ * C_ * HW_];
// transformed quantized weights: [tap(9)][ci(64)][co(64)]
__device__ float g_wq[9 * 64 * 64];

// ---------------------------------------------------------------------------
// Kernel 1: per-pixel (across channel) LN + int8 fake-quant.
// One thread per pixel; 64 channel loads each warp-coalesced (stride HW).
// ---------------------------------------------------------------------------
__global__ void __launch_bounds__(128) norm_quant_kernel(const float* __restrict__ x) {
    int p = blockIdx.x * 128 + threadIdx.x;   // 0 .. BHW-1
    int b  = p >> 16;       // / HW_ (HW_ = 65536)
    int sp = p & 65535;

    const float* xb = x + (size_t)b * C_ * HW_ + sp;

    float v[64];
    float sum = 0.f;
#pragma unroll
    for (int c = 0; c < 64; c++) {
        v[c] = xb[(size_t)c * HW_];
        sum += v[c];
    }
    float mu = sum * (1.0f / 64.0f);

    float var = 0.f, mx = 0.f;
#pragma unroll
    for (int c = 0; c < 64; c++) {
        float d = v[c] - mu;
        var += d * d;
        mx = fmaxf(mx, fabsf(d));
    }
    var *= (1.0f / 64.0f);
    float r = rsqrtf(var + 1e-8f);

    float maxn = fmaxf(mx * r, 1e-8f);
    float s     = 127.0f / maxn;
    float inv_s = maxn * (1.0f / 127.0f);

    float* yb = g_y + (size_t)b * C_ * HW_ + sp;
#pragma unroll
    for (int c = 0; c < 64; c++) {
        float q = rintf(s * (r * (v[c] - mu)));   // round-half-even == jnp.round
        q = fminf(fmaxf(q, -128.f), 127.f);
        yb[(size_t)c * HW_] = q * inv_s;
    }
}

// ---------------------------------------------------------------------------
// Kernel 2: ternary weight quant + layout transform OIHW -> [tap][ci][co]
// Single block; trivial cost.
// ---------------------------------------------------------------------------
__global__ void __launch_bounds__(512) wq_kernel(const float* __restrict__ Wt) {
    __shared__ float red[16];
    __shared__ float s_w_sh;
    int tid = threadIdx.x;

    float sum = 0.f;
    for (int i = tid; i < 36864; i += 512) sum += fabsf(Wt[i]);
#pragma unroll
    for (int o = 16; o; o >>= 1) sum += __shfl_xor_sync(0xffffffffu, sum, o);
    if ((tid & 31) == 0) red[tid >> 5] = sum;
    __syncthreads();
    if (tid < 32) {
        float s2 = (tid < 16) ? red[tid] : 0.f;
#pragma unroll
        for (int o = 8; o; o >>= 1) s2 += __shfl_xor_sync(0xffffffffu, s2, o);
        if (tid == 0) {
            float mean = s2 * (1.0f / 36864.0f);
            s_w_sh = 1.0f / fmaxf(mean, 1e-8f);
        }
    }
    __syncthreads();
    float s_w = s_w_sh;

    for (int i = tid; i < 36864; i += 512) {
        float t = rintf(s_w * Wt[i]);
        t = fminf(fmaxf(t, -1.f), 1.f);
        int co  = i / 576;            // 576 = 64*9
        int rem = i - co * 576;
        int ci  = rem / 9;
        int tap = rem - ci * 9;
        g_wq[(tap * 64 + ci) * 64 + co] = t / s_w;
    }
}

// ---------------------------------------------------------------------------
// Kernel 3: direct conv, smem-tiled.
// Block: (bx,h,b) -> 64 output cols (w0..w0+63) x 1 row x all 64 cout.
// smem: input tile ys[3][64][68] (rows h-1..h+1, cols w0-1..w0+64, all ci)
//       per-tap weight tile ws[64][64].
// 128 threads, each computes 4 px x 8 co.
// ---------------------------------------------------------------------------
#define YS_STRIDE 68
#define YS_FLOATS (3 * 64 * YS_STRIDE)     // 13056
#define WS_FLOATS (64 * 64)                // 4096
#define CONV_SMEM_BYTES ((YS_FLOATS + WS_FLOATS) * 4)   // 68608

__global__ void __launch_bounds__(128) conv_kernel(const float* __restrict__ bias,
                                                   float* __restrict__ out) {
    extern __shared__ float smem[];
    float* ys = smem;                 // [3][64][68]
    float* ws = smem + YS_FLOATS;     // [64][64]

    int bx = blockIdx.x;              // 0..3
    int h  = blockIdx.y;              // 0..255
    int b  = blockIdx.z;              // 0..7
    int tid = threadIdx.x;
    int w0 = bx * 64;

    // load input tile (zero-padded at borders)
    const float* yb = g_y + (size_t)b * C_ * HW_;
    for (int idx = tid; idx < 3 * 64 * 66; idx += 128) {
        int r   = idx / (64 * 66);
        int rem = idx - r * (64 * 66);
        int ci  = rem / 66;
        int col = rem - ci * 66;
        int hh = h + r - 1;
        int ww = w0 + col - 1;
        float val = 0.f;
        if (hh >= 0 && hh < H_ && ww >= 0 && ww < W_)
            val = yb[(size_t)ci * HW_ + hh * W_ + ww];
        ys[(r * 64 + ci) * YS_STRIDE + col] = val;
    }

    int pxg = tid >> 3;               // 0..15
    int cog = tid & 7;                // 0..7
    int px0 = pxg * 4;
    int co0 = cog * 8;

    float acc[4][8];
#pragma unroll
    for (int j = 0; j < 4; j++)
#pragma unroll
        for (int k = 0; k < 8; k++) acc[j][k] = 0.f;

#pragma unroll
    for (int tap = 0; tap < 9; tap++) {
        __syncthreads();   // ys ready (tap0) / previous-tap compute done
        const float* wt = g_wq + tap * 4096;
        for (int idx = tid; idx < 4096; idx += 128) ws[idx] = wt[idx];
        __syncthreads();

        int kh = tap / 3;
        int kw = tap - kh * 3;
        const float* ysrow = ys + kh * 64 * YS_STRIDE + px0 + kw;

#pragma unroll 4
        for (int ci = 0; ci < 64; ci++) {
            float a0 = ysrow[ci * YS_STRIDE + 0];
            float a1 = ysrow[ci * YS_STRIDE + 1];
            float a2 = ysrow[ci * YS_STRIDE + 2];
            float a3 = ysrow[ci * YS_STRIDE + 3];
            float4 wv0 = *(const float4*)(ws + ci * 64 + co0);
            float4 wv1 = *(const float4*)(ws + ci * 64 + co0 + 4);
            float wvs[8] = {wv0.x, wv0.y, wv0.z, wv0.w, wv1.x, wv1.y, wv1.z, wv1.w};
#pragma unroll
            for (int k = 0; k < 8; k++) {
                acc[0][k] = fmaf(a0, wvs[k], acc[0][k]);
                acc[1][k] = fmaf(a1, wvs[k], acc[1][k]);
                acc[2][k] = fmaf(a2, wvs[k], acc[2][k]);
                acc[3][k] = fmaf(a3, wvs[k], acc[3][k]);
            }
        }
    }

    // write out: NCHW
#pragma unroll
    for (int k = 0; k < 8; k++) {
        int co = co0 + k;
        float bv = bias[co];
        float* op = out + ((size_t)(b * 64 + co)) * HW_ + h * W_ + w0 + px0;
        float4 o4 = make_float4(acc[0][k] + bv, acc[1][k] + bv,
                                acc[2][k] + bv, acc[3][k] + bv);
        *(float4*)op = o4;
    }
}

// ---------------------------------------------------------------------------
extern "C" void kernel_launch(void* const* d_in, const int* in_sizes, int n_in,
                              void* d_out, int out_size) {
    (void)in_sizes; (void)n_in; (void)out_size;
    const float* x    = (const float*)d_in[0];
    const float* Wt   = (const float*)d_in[1];
    const float* bias = (const float*)d_in[2];
    float* out = (float*)d_out;

    cudaFuncSetAttribute(conv_kernel, cudaFuncAttributeMaxDynamicSharedMemorySize,
                         CONV_SMEM_BYTES);

    norm_quant_kernel<<<BHW_ / 128, 128>>>(x);
    wq_kernel<<<1, 512>>>(Wt);

    dim3 grid(W_ / 64, H_, B_);
    conv_kernel<<<grid, 128, CONV_SMEM_BYTES>>>(bias, out);
}

// round 3
// speedup vs baseline: 8.8427x; 8.8427x over previous
#include <cuda_runtime.h>
#include <cuda_fp16.h>
#include <cstdint>
#include <math.h>

// ===========================================================================
// MMFConv2d sm_103a (base-target-safe): per-pixel channel-LN + int8 fake-quant
// -> fp16 NHWC; ternary weights exact fp16; 3x3 conv = 9 shifted HMMA GEMMs
// (mma.sync m16n8k16 f32 acc); scale+bias fp32 epilogue.
// ===========================================================================

#define B_ 8
#define H_ 256
#define W_ 256
#define HW_ 65536
#define NTILES 2048            // B * H  (one image row per tile)

// activations NHWC fp16: [b][h][w][ci]
__device__ __half g_a[(size_t)B_ * HW_ * 64];
// ternary weights fp16 exact: [tap][co][ci]
__device__ __half g_w[9 * 64 * 64];
__device__ float g_inv_sw;

// ---------------------------------------------------------------------------
__device__ __forceinline__ uint32_t smem_u32(const void* p) {
    uint32_t a;
    asm("{ .reg .u64 t; cvta.to.shared.u64 t, %1; cvt.u32.u64 %0, t; }"
        : "=r"(a) : "l"(p));
    return a;
}

__device__ __forceinline__ void ldsm_x4(uint32_t (&r)[4], uint32_t a) {
    asm volatile("ldmatrix.sync.aligned.m8n8.x4.shared.b16 {%0,%1,%2,%3}, [%4];"
                 : "=r"(r[0]), "=r"(r[1]), "=r"(r[2]), "=r"(r[3]) : "r"(a));
}
__device__ __forceinline__ void ldsm_x2(uint32_t (&r)[2], uint32_t a) {
    asm volatile("ldmatrix.sync.aligned.m8n8.x2.shared.b16 {%0,%1}, [%2];"
                 : "=r"(r[0]), "=r"(r[1]) : "r"(a));
}
__device__ __forceinline__ void mma16816(float (&d)[4], const uint32_t (&a)[4],
                                         const uint32_t (&b)[2]) {
    asm volatile(
        "mma.sync.aligned.m16n8k16.row.col.f32.f16.f16.f32 "
        "{%0,%1,%2,%3}, {%4,%5,%6,%7}, {%8,%9}, {%0,%1,%2,%3};"
        : "+f"(d[0]), "+f"(d[1]), "+f"(d[2]), "+f"(d[3])
        : "r"(a[0]), "r"(a[1]), "r"(a[2]), "r"(a[3]), "r"(b[0]), "r"(b[1]));
}

#define CP_ASYNC(dst, src, n) \
    asm volatile("cp.async.cg.shared.global [%0], [%1], 16, %2;" \
                 :: "r"(dst), "l"(src), "r"(n) : "memory")
#define CP_COMMIT() asm volatile("cp.async.commit_group;" ::: "memory")
#define CP_WAIT0()  asm volatile("cp.async.wait_group 0;" ::: "memory")

// ---------------------------------------------------------------------------
// Kernel 1: per-pixel LN + int8 fake-quant -> fp16 NHWC
// ---------------------------------------------------------------------------
__global__ void __launch_bounds__(128) norm_quant_kernel(const float* __restrict__ x) {
    int p  = blockIdx.x * 128 + threadIdx.x;
    int b  = p >> 16;
    int sp = p & 65535;

    const float* xb = x + (size_t)b * 64 * HW_ + sp;

    float v[64];
    float sum = 0.f;
#pragma unroll
    for (int c = 0; c < 64; c++) { v[c] = xb[(size_t)c * HW_]; sum += v[c]; }
    float mu = sum * (1.0f / 64.0f);

    float var = 0.f, mx = 0.f;
#pragma unroll
    for (int c = 0; c < 64; c++) {
        float d = v[c] - mu;
        var += d * d;
        mx = fmaxf(mx, fabsf(d));
    }
    var *= (1.0f / 64.0f);
    float r = rsqrtf(var + 1e-8f);

    float maxn  = fmaxf(mx * r, 1e-8f);
    float s     = 127.0f / maxn;
    float inv_s = maxn * (1.0f / 127.0f);

    __half* yb = g_a + (size_t)p * 64;
#pragma unroll
    for (int c = 0; c < 64; c += 8) {
        uint4 u;
        __half2 h2;
        float q0, q1;
#define QV(cc) fminf(fmaxf(rintf(s * (r * (v[cc] - mu))), -128.f), 127.f) * inv_s
        q0 = QV(c + 0); q1 = QV(c + 1); h2 = __floats2half2_rn(q0, q1); u.x = *(uint32_t*)&h2;
        q0 = QV(c + 2); q1 = QV(c + 3); h2 = __floats2half2_rn(q0, q1); u.y = *(uint32_t*)&h2;
        q0 = QV(c + 4); q1 = QV(c + 5); h2 = __floats2half2_rn(q0, q1); u.z = *(uint32_t*)&h2;
        q0 = QV(c + 6); q1 = QV(c + 7); h2 = __floats2half2_rn(q0, q1); u.w = *(uint32_t*)&h2;
#undef QV
        *(uint4*)(yb + c) = u;
    }
}

// ---------------------------------------------------------------------------
// Kernel 2: ternary weight quant -> exact fp16 in [tap][co][ci]
// ---------------------------------------------------------------------------
__global__ void __launch_bounds__(512) wq_kernel(const float* __restrict__ Wt) {
    __shared__ float red[16];
    __shared__ float s_w_sh;
    int tid = threadIdx.x;

    float sum = 0.f;
    for (int i = tid; i < 36864; i += 512) sum += fabsf(Wt[i]);
#pragma unroll
    for (int o = 16; o; o >>= 1) sum += __shfl_xor_sync(0xffffffffu, sum, o);
    if ((tid & 31) == 0) red[tid >> 5] = sum;
    __syncthreads();
    if (tid < 32) {
        float s2 = (tid < 16) ? red[tid] : 0.f;
#pragma unroll
        for (int o = 8; o; o >>= 1) s2 += __shfl_xor_sync(0xffffffffu, s2, o);
        if (tid == 0) {
            float mean = s2 * (1.0f / 36864.0f);
            float inv_sw = fmaxf(mean, 1e-8f);
            s_w_sh = 1.0f / inv_sw;
            g_inv_sw = inv_sw;
        }
    }
    __syncthreads();
    float s_w = s_w_sh;

    for (int i = tid; i < 36864; i += 512) {
        float t = rintf(s_w * Wt[i]);
        t = fminf(fmaxf(t, -1.f), 1.f);
        int co  = i / 576;
        int rem = i - co * 576;
        int ci  = rem / 9;
        int tap = rem - ci * 9;
        g_w[(tap * 64 + co) * 64 + ci] = __float2half_rn(t);   // exact
    }
}

// ---------------------------------------------------------------------------
// Kernel 3: persistent HMMA conv. CTA tile = 1 image row (256 px) x 64 co.
// 8 warps, each 32px x 64co. smem: 9 weight tiles + 3 halo'd act rows.
// Swizzle: byte off = q*128 + c  ->  q*128 + (c ^ ((q&7)<<4))
// ---------------------------------------------------------------------------
#define WS_OFF      0                         // 9 * 8192 = 73728
#define ACT_OFF     73728
#define ACT_ROW_B   33792                     // 264 rows * 128B (1024-aligned)
#define BIAS_OFF    (ACT_OFF + 3 * ACT_ROW_B) // 175104
#define SMEM_BYTES  (BIAS_OFF + 256)          // 175360

__global__ void __launch_bounds__(256, 1) conv_kernel(const float* __restrict__ bias,
                                                      float* __restrict__ out) {
    extern __shared__ __align__(1024) unsigned char smem[];
    uint32_t sb = smem_u32(smem);
    int tid = threadIdx.x, wid = tid >> 5, lane = tid & 31;

    // ---- weights -> smem (swizzled), bias -> smem ----
    for (int i = tid; i < 4608; i += 256) {         // (tap, co, c) 16B granules
        int tap = i >> 9;
        int r   = i & 511;
        int co  = r >> 3;
        int c   = r & 7;
        uint32_t dst = sb + WS_OFF + (tap << 13) + co * 128 + ((c << 4) ^ ((co & 7) << 4));
        const char* src = (const char*)g_w + (size_t)i * 16;
        CP_ASYNC(dst, src, 16u);
    }
    if (tid < 64) ((float*)(smem + BIAS_OFF))[tid] = bias[tid];
    CP_COMMIT();

    float inv_sw = g_inv_sw;

    // per-thread ldmatrix lane geometry
    int rA   = (lane & 7) | (lane & 8);             // A fragment row 0..15
    int colA = (lane & 16);                         // 0 or 16 bytes (k 0-7 / 8-15)
    int l16  = lane & 15;
    int rB   = l16 & 7;
    int colB = (l16 & 8) << 1;                      // 0 or 16
    uint32_t rowBterm = (uint32_t)(rB << 7);
    uint32_t cxB = (uint32_t)(colB ^ (rB << 4));

    int px_base = wid * 32;
    uint32_t rowbaseA[3], cxA[3];
#pragma unroll
    for (int kw = 0; kw < 3; kw++) {
        rowbaseA[kw] = (uint32_t)((px_base + kw + rA) << 7);
        cxA[kw]      = (uint32_t)(colA ^ (((rA + kw) & 7) << 4));
    }

    int qrow = lane >> 2;
    int qcol = (lane & 3) << 1;

    for (int t = blockIdx.x; t < NTILES; t += gridDim.x) {
        int b = t >> 8;
        int h = t & 255;

        __syncthreads();   // previous tile's compute done before overwriting act

        // ---- load 3 halo'd activation rows (258 px x 128B each) ----
#pragma unroll
        for (int r = 0; r < 3; r++) {
            int hh = h + r - 1;
            unsigned hok = ((unsigned)hh < 256u);
            for (int i = tid; i < 2064; i += 256) {     // 258*8 granules
                int px = i >> 3, c = i & 7;
                int w  = px - 1;
                unsigned ok = hok & ((unsigned)w < 256u);
                const char* src = (const char*)g_a
                    + ((((size_t)b << 16) + ((size_t)(hok ? hh : 0) << 8) + (ok ? w : 0)) << 7)
                    + (c << 4);
                uint32_t dst = sb + ACT_OFF + r * ACT_ROW_B
                             + px * 128 + ((c << 4) ^ ((px & 7) << 4));
                CP_ASYNC(dst, src, ok ? 16u : 0u);
            }
        }
        CP_COMMIT();
        CP_WAIT0();
        __syncthreads();

        // ---- compute: 9 taps x 4 k16-chunks ----
        float acc[2][8][4];
#pragma unroll
        for (int m = 0; m < 2; m++)
#pragma unroll
            for (int n = 0; n < 8; n++)
#pragma unroll
                for (int e = 0; e < 4; e++) acc[m][n][e] = 0.f;

#pragma unroll 1
        for (int tap = 0; tap < 9; tap++) {
            int kh = tap / 3, kw = tap - kh * 3;
            uint32_t abuf  = sb + ACT_OFF + kh * ACT_ROW_B + rowbaseA[kw];
            uint32_t wbase = sb + WS_OFF + (tap << 13) + rowBterm;
            uint32_t cxa   = cxA[kw];
#pragma unroll
            for (int kk = 0; kk < 4; kk++) {
                uint32_t a0[4], a1[4];
                ldsm_x4(a0, abuf + (((uint32_t)kk << 5) ^ cxa));
                ldsm_x4(a1, abuf + 2048 + (((uint32_t)kk << 5) ^ cxa));
                uint32_t kB = ((uint32_t)kk << 5) ^ cxB;
#pragma unroll
                for (int n = 0; n < 8; n++) {
                    uint32_t bf[2];
                    ldsm_x2(bf, wbase + ((uint32_t)n << 10) + kB);
                    mma16816(acc[0][n], a0, bf);
                    mma16816(acc[1][n], a1, bf);
                }
            }
        }

        // ---- epilogue: scale + bias, fp32 NCHW stores ----
        const float* bs = (const float*)(smem + BIAS_OFF);
#pragma unroll
        for (int m = 0; m < 2; m++) {
            int px = px_base + m * 16 + qrow;
            float* prow = out + ((size_t)b << 22) + ((size_t)h << 8) + px;
#pragma unroll
            for (int n = 0; n < 8; n++) {
                int co = n * 8 + qcol;
                float b0 = bs[co], b1 = bs[co + 1];
                float* p0 = prow + ((size_t)co << 16);
                float* p1 = prow + ((size_t)(co + 1) << 16);
                p0[0] = acc[m][n][0] * inv_sw + b0;
                p1[0] = acc[m][n][1] * inv_sw + b1;
                p0[8] = acc[m][n][2] * inv_sw + b0;
                p1[8] = acc[m][n][3] * inv_sw + b1;
            }
        }
    }
}

// ---------------------------------------------------------------------------
extern "C" void kernel_launch(void* const* d_in, const int* in_sizes, int n_in,
                              void* d_out, int out_size) {
    (void)in_sizes; (void)n_in; (void)out_size;
    const float* x    = (const float*)d_in[0];
    const float* Wt   = (const float*)d_in[1];
    const float* bias = (const float*)d_in[2];
    float* out = (float*)d_out;

    cudaFuncSetAttribute(conv_kernel, cudaFuncAttributeMaxDynamicSharedMemorySize,
                         SMEM_BYTES);

    norm_quant_kernel<<<B_ * HW_ / 128, 128>>>(x);
    wq_kernel<<<1, 512>>>(Wt);
    conv_kernel<<<152, 256, SMEM_BYTES>>>(bias, out);
}

// round 7
// speedup vs baseline: 9.3895x; 1.0618x over previous
#include <cuda_runtime.h>
#include <cuda_fp16.h>
#include <cstdint>
#include <math.h>

// ===========================================================================
// MMFConv2d sm_103a (base-target-safe), Round 7:
//   K1 (R3-proven): per-pixel channel-LN + int8 fake-quant -> fp16 NHWC
//       (y_tilde = q * inv_s stored in fp16: q is an int <=8 bits -> near exact)
//   K2 (R3-proven): ternary weight quant -> exact fp16 {-1,0,1} [tap][co][ci]
//   K3: conv = 9 shifted HMMA GEMMs (m16n8k16 f32 acc), R6-proven
//       double-buffered grid-stride skeleton, 128-px tiles, 4 warps x 32 px.
// ===========================================================================

#define NTILES 4096            // B * H * 2 half-rows

__device__ __half g_a[(size_t)8 * 65536 * 64];   // fp16 NHWC activations
__device__ __half g_w[9 * 64 * 64];              // fp16 ternary weights
__device__ float g_inv_sw;

// ---------------------------------------------------------------------------
__device__ __forceinline__ uint32_t smem_u32(const void* p) {
    uint32_t a;
    asm("{ .reg .u64 t; cvta.to.shared.u64 t, %1; cvt.u32.u64 %0, t; }"
        : "=r"(a) : "l"(p));
    return a;
}
__device__ __forceinline__ void ldsm_x4(uint32_t (&r)[4], uint32_t a) {
    asm volatile("ldmatrix.sync.aligned.m8n8.x4.shared.b16 {%0,%1,%2,%3}, [%4];"
                 : "=r"(r[0]), "=r"(r[1]), "=r"(r[2]), "=r"(r[3]) : "r"(a));
}
__device__ __forceinline__ void ldsm_x2(uint32_t (&r)[2], uint32_t a) {
    asm volatile("ldmatrix.sync.aligned.m8n8.x2.shared.b16 {%0,%1}, [%2];"
                 : "=r"(r[0]), "=r"(r[1]) : "r"(a));
}
__device__ __forceinline__ void mma16816(float (&d)[4], const uint32_t (&a)[4],
                                         const uint32_t (&b)[2]) {
    asm volatile(
        "mma.sync.aligned.m16n8k16.row.col.f32.f16.f16.f32 "
        "{%0,%1,%2,%3}, {%4,%5,%6,%7}, {%8,%9}, {%0,%1,%2,%3};"
        : "+f"(d[0]), "+f"(d[1]), "+f"(d[2]), "+f"(d[3])
        : "r"(a[0]), "r"(a[1]), "r"(a[2]), "r"(a[3]), "r"(b[0]), "r"(b[1]));
}
#define CP_ASYNC(dst, src, n) \
    asm volatile("cp.async.cg.shared.global [%0], [%1], 16, %2;" \
                 :: "r"(dst), "l"(src), "r"(n) : "memory")
#define CP_COMMIT() asm volatile("cp.async.commit_group;" ::: "memory")
#define CP_WAIT0()  asm volatile("cp.async.wait_group 0;" ::: "memory")
#define CP_WAIT1()  asm volatile("cp.async.wait_group 1;" ::: "memory")

// ---------------------------------------------------------------------------
// smem layout: fp16 act rows are 128B (one px = 64ch), R3 swizzle over 8 chunks
// ---------------------------------------------------------------------------
#define SLOT_B     16640                    // 130 px * 128 B
#define ABUF_B     (3 * SLOT_B)             // 49920
#define WS_OFF     0                        // 9 * 8192 = 73728
#define ACT_OFF    73728                    // 2 buffers * 49920
#define BIAS_OFF   (ACT_OFF + 2 * ABUF_B)   // 173568
#define SMEM_BYTES (BIAS_OFF + 256)         // 173824

// ---------------------------------------------------------------------------
// Kernel 1 (R3-proven): per-pixel LN + int8 fake-quant -> fp16 NHWC
// ---------------------------------------------------------------------------
__global__ void __launch_bounds__(128) norm_quant_kernel(const float* __restrict__ x) {
    int p  = blockIdx.x * 128 + threadIdx.x;
    int b  = p >> 16;
    int sp = p & 65535;

    const float* xb = x + (size_t)b * 64 * 65536 + sp;

    float v[64];
    float sum = 0.f;
#pragma unroll
    for (int c = 0; c < 64; c++) { v[c] = xb[(size_t)c << 16]; sum += v[c]; }
    float mu = sum * (1.0f / 64.0f);

    float var = 0.f, mx = 0.f;
#pragma unroll
    for (int c = 0; c < 64; c++) {
        float d = v[c] - mu;
        var += d * d;
        mx = fmaxf(mx, fabsf(d));
    }
    var *= (1.0f / 64.0f);
    float r = rsqrtf(var + 1e-8f);

    float maxn  = fmaxf(mx * r, 1e-8f);
    float s     = 127.0f / maxn;
    float inv_s = maxn * (1.0f / 127.0f);

    __half* yb = g_a + ((size_t)p << 6);
#pragma unroll
    for (int c = 0; c < 64; c += 8) {
        uint4 u;
        __half2 h2;
        float q0, q1;
#define QV(cc) fminf(fmaxf(rintf(s * (r * (v[cc] - mu))), -128.f), 127.f) * inv_s
        q0 = QV(c + 0); q1 = QV(c + 1); h2 = __floats2half2_rn(q0, q1); u.x = *(uint32_t*)&h2;
        q0 = QV(c + 2); q1 = QV(c + 3); h2 = __floats2half2_rn(q0, q1); u.y = *(uint32_t*)&h2;
        q0 = QV(c + 4); q1 = QV(c + 5); h2 = __floats2half2_rn(q0, q1); u.z = *(uint32_t*)&h2;
        q0 = QV(c + 6); q1 = QV(c + 7); h2 = __floats2half2_rn(q0, q1); u.w = *(uint32_t*)&h2;
#undef QV
        *(uint4*)(yb + c) = u;
    }
}

// ---------------------------------------------------------------------------
// Kernel 2 (R3-proven): ternary weight quant -> exact fp16 [tap][co][ci]
// ---------------------------------------------------------------------------
__global__ void __launch_bounds__(512) wq_kernel(const float* __restrict__ Wt) {
    __shared__ float red[16];
    __shared__ float s_w_sh;
    int tid = threadIdx.x;

    float sum = 0.f;
    for (int i = tid; i < 36864; i += 512) sum += fabsf(Wt[i]);
#pragma unroll
    for (int o = 16; o; o >>= 1) sum += __shfl_xor_sync(0xffffffffu, sum, o);
    if ((tid & 31) == 0) red[tid >> 5] = sum;
    __syncthreads();
    if (tid < 32) {
        float s2 = (tid < 16) ? red[tid] : 0.f;
#pragma unroll
        for (int o = 8; o; o >>= 1) s2 += __shfl_xor_sync(0xffffffffu, s2, o);
        if (tid == 0) {
            float mean = s2 * (1.0f / 36864.0f);
            float inv_sw = fmaxf(mean, 1e-8f);
            s_w_sh = 1.0f / inv_sw;
            g_inv_sw = inv_sw;
        }
    }
    __syncthreads();
    float s_w = s_w_sh;

    for (int i = tid; i < 36864; i += 512) {
        float t = rintf(s_w * Wt[i]);
        t = fminf(fmaxf(t, -1.f), 1.f);
        int co  = i / 576;
        int rem = i - co * 576;
        int ci  = rem / 9;
        int tap = rem - ci * 9;
        g_w[(tap * 64 + co) * 64 + ci] = __float2half_rn(t);   // exact
    }
}

// ---------------------------------------------------------------------------
// act tile load: 3 halo'd rows x 130 px x 128B (fp16) into buffer buf.
// global fp16 NHWC: byte = ((b<<16 | h<<8 | w) << 7) | c<<4, c = 16B chunk 0..7
// smem swizzle (R3-proven): loc*128 + ((c ^ (loc & 7)) << 4)
// ---------------------------------------------------------------------------
__device__ __forceinline__ void load_tile(uint32_t sb, int t, int buf, int tid) {
    int b   = t >> 9;
    int rem = t & 511;
    int h   = rem >> 1;
    int w0  = (rem & 1) << 7;
    uint32_t base = sb + ACT_OFF + buf * ABUF_B;
    size_t gb = ((size_t)b << 16);
    for (int i = tid; i < 3120; i += 128) {       // 3 * 130 * 8
        int r    = i / 1040;
        int rem2 = i - r * 1040;
        int loc  = rem2 >> 3;                     // 0..129
        int c    = rem2 & 7;
        int hh   = h + r - 1;
        int w    = w0 + loc - 1;
        unsigned ok = (((unsigned)hh < 256u) & ((unsigned)w < 256u)) ? 1u : 0u;
        size_t off = ((gb | ((size_t)(ok ? hh : 0) << 8) | (size_t)(ok ? w : 0)) << 7)
                   | ((size_t)c << 4);
        uint32_t dst = base + r * SLOT_B + (loc << 7) + ((c ^ (loc & 7)) << 4);
        CP_ASYNC(dst, (const char*)g_a + off, ok ? 16u : 0u);
    }
}

// ---------------------------------------------------------------------------
// Kernel 3: conv. 128 threads, 4 warps; warp w -> px [32w, 32w+32) x 64 co.
// Grid-stride over 4096 (b,h,half-row) tiles; double-buffered act tile.
// ---------------------------------------------------------------------------
__global__ void __launch_bounds__(128, 1) conv_kernel(const float* __restrict__ bias,
                                                      float* __restrict__ out) {
    extern __shared__ __align__(1024) unsigned char smem[];
    uint32_t sb = smem_u32(smem);
    int tid = threadIdx.x, wid = tid >> 5, lane = tid & 31;

    // ---- weights -> smem (R3 swizzle: 128B rows, 8 chunks), bias ----
    for (int i = tid; i < 4608; i += 128) {
        int tap = i >> 9;
        int r   = i & 511;
        int co  = r >> 3;
        int c   = r & 7;
        uint32_t dst = sb + WS_OFF + (tap << 13) + (co << 7) + ((c ^ (co & 7)) << 4);
        CP_ASYNC(dst, (const char*)g_w + ((size_t)i << 4), 16u);
    }
    if (tid < 64) ((float*)(smem + BIAS_OFF))[tid] = bias[tid];
    CP_COMMIT();
    float inv_sw = g_inv_sw;

    // ---- per-thread ldmatrix geometry (R3-proven) ----
    int rA   = lane & 15;
    int colA = lane & 16;                     // 0/16 byte: k lo/hi half of 32B
    int l16  = lane & 15;
    int rB   = l16 & 7;
    int colB = (l16 & 8) << 1;                // 0/16
    uint32_t rowBterm = (uint32_t)(rB << 7);
    uint32_t cxB = (uint32_t)(colB ^ (rB << 4));
    uint32_t rowbaseA[3], cxA[3];
#pragma unroll
    for (int kw = 0; kw < 3; kw++) {
        int loc = wid * 32 + kw + rA;         // slot row for A0 rows 0..15
        rowbaseA[kw] = (uint32_t)(loc << 7);
        cxA[kw]      = (uint32_t)(colA ^ ((loc & 7) << 4));
    }
    int qr = lane >> 2, qc = (lane & 3) << 1;

    int stride = gridDim.x;
    int t0 = blockIdx.x;
    load_tile(sb, t0, 0, tid);
    CP_COMMIT();

    int j = 0;
    for (int t = t0; t < NTILES; t += stride, j++) {
        int tn = t + stride;
        int hn = (tn < NTILES);
        if (hn) { load_tile(sb, tn, (j + 1) & 1, tid); CP_COMMIT(); }
        if (hn) { CP_WAIT1(); } else { CP_WAIT0(); }
        __syncthreads();

        int b   = t >> 9;
        int rem = t & 511;
        int h   = rem >> 1;
        int w0  = (rem & 1) << 7;
        uint32_t bb = sb + ACT_OFF + (j & 1) * ABUF_B;

        // ---- 9-tap HMMA ----
        float acc[2][8][4];
#pragma unroll
        for (int m = 0; m < 2; m++)
#pragma unroll
            for (int n = 0; n < 8; n++)
#pragma unroll
                for (int e = 0; e < 4; e++) acc[m][n][e] = 0.f;

#pragma unroll
        for (int tap = 0; tap < 9; tap++) {
            int kh = tap / 3, kw = tap - kh * 3;
            uint32_t wbase = sb + WS_OFF + (tap << 13) + rowBterm;
            uint32_t abuf  = bb + kh * SLOT_B + rowbaseA[kw];
            uint32_t cxa   = cxA[kw];
#pragma unroll
            for (int kk = 0; kk < 4; kk++) {
                uint32_t a0[4], a1[4];
                ldsm_x4(a0, abuf + (((uint32_t)kk << 5) ^ cxa));
                ldsm_x4(a1, abuf + 2048 + (((uint32_t)kk << 5) ^ cxa));
                uint32_t kB = ((uint32_t)kk << 5) ^ cxB;
#pragma unroll
                for (int n = 0; n < 8; n++) {
                    uint32_t bf[2];
                    ldsm_x2(bf, wbase + ((uint32_t)n << 10) + kB);
                    mma16816(acc[0][n], a0, bf);
                    mma16816(acc[1][n], a1, bf);
                }
            }
        }

        // ---- epilogue: weight-scale + bias, fp32 NCHW ----
        const float* bs = (const float*)(smem + BIAS_OFF);
        float* ob = out + ((size_t)b << 22) + ((size_t)h << 8) + w0;
#pragma unroll
        for (int m = 0; m < 2; m++) {
            int px = wid * 32 + 16 * m + qr;
#pragma unroll
            for (int n = 0; n < 8; n++) {
                int co = (n << 3) + qc;
                float bc0 = bs[co], bc1 = bs[co + 1];
                float* o0 = ob + ((size_t)co << 16) + px;
                float* o1 = ob + ((size_t)(co + 1) << 16) + px;
                o0[0] = acc[m][n][0] * inv_sw + bc0;
                o1[0] = acc[m][n][1] * inv_sw + bc1;
                o0[8] = acc[m][n][2] * inv_sw + bc0;
                o1[8] = acc[m][n][3] * inv_sw + bc1;
            }
        }
        __syncthreads();     // reads of this buffer done before j+2 overwrites
    }
}

// ---------------------------------------------------------------------------
extern "C" void kernel_launch(void* const* d_in, const int* in_sizes, int n_in,
                              void* d_out, int out_size) {
    (void)in_sizes; (void)n_in; (void)out_size;
    const float* x    = (const float*)d_in[0];
    const float* Wt   = (const float*)d_in[1];
    const float* bias = (const float*)d_in[2];
    float* out = (float*)d_out;

    cudaFuncSetAttribute(conv_kernel, cudaFuncAttributeMaxDynamicSharedMemorySize,
                         SMEM_BYTES);

    norm_quant_kernel<<<8 * 65536 / 128, 128>>>(x);
    wq_kernel<<<1, 512>>>(Wt);
    conv_kernel<<<152, 128, SMEM_BYTES>>>(bias, out);
}

// round 8
// speedup vs baseline: 9.8676x; 1.0509x over previous
#include <cuda_runtime.h>
#include <cuda_fp16.h>
#include <cstdint>
#include <math.h>

// ===========================================================================
// MMFConv2d sm_103a (base-target-safe), Round 8:
//   K1: per-pixel channel-LN + int8 fake-quant -> fp16 NHWC (proven)
//   K2: ternary weight quant -> exact fp16 [tap][co][ci] (proven)
//   K3: conv = 9 shifted HMMA GEMMs. 8 warps x (64px x 64co), tile = 2 rows
//       x 256 px, 4-slot row ring, tap-phased prefetch (kh=0 frees row h-1,
//       kh=1 frees row h), 19x8 strip grid.
// ===========================================================================

__device__ __half g_a[(size_t)8 * 65536 * 64];   // fp16 NHWC activations
__device__ __half g_w[9 * 64 * 64];              // fp16 ternary weights
__device__ float g_inv_sw;

// ---------------------------------------------------------------------------
__device__ __forceinline__ uint32_t smem_u32(const void* p) {
    uint32_t a;
    asm("{ .reg .u64 t; cvta.to.shared.u64 t, %1; cvt.u32.u64 %0, t; }"
        : "=r"(a) : "l"(p));
    return a;
}
__device__ __forceinline__ void ldsm_x4(uint32_t (&r)[4], uint32_t a) {
    asm volatile("ldmatrix.sync.aligned.m8n8.x4.shared.b16 {%0,%1,%2,%3}, [%4];"
                 : "=r"(r[0]), "=r"(r[1]), "=r"(r[2]), "=r"(r[3]) : "r"(a));
}
__device__ __forceinline__ void ldsm_x2(uint32_t (&r)[2], uint32_t a) {
    asm volatile("ldmatrix.sync.aligned.m8n8.x2.shared.b16 {%0,%1}, [%2];"
                 : "=r"(r[0]), "=r"(r[1]) : "r"(a));
}
__device__ __forceinline__ void mma16816(float (&d)[4], const uint32_t (&a)[4],
                                         const uint32_t (&b)[2]) {
    asm volatile(
        "mma.sync.aligned.m16n8k16.row.col.f32.f16.f16.f32 "
        "{%0,%1,%2,%3}, {%4,%5,%6,%7}, {%8,%9}, {%0,%1,%2,%3};"
        : "+f"(d[0]), "+f"(d[1]), "+f"(d[2]), "+f"(d[3])
        : "r"(a[0]), "r"(a[1]), "r"(a[2]), "r"(a[3]), "r"(b[0]), "r"(b[1]));
}
#define CP_ASYNC(dst, src, n) \
    asm volatile("cp.async.cg.shared.global [%0], [%1], 16, %2;" \
                 :: "r"(dst), "l"(src), "r"(n) : "memory")
#define CP_COMMIT() asm volatile("cp.async.commit_group;" ::: "memory")
#define CP_WAIT0()  asm volatile("cp.async.wait_group 0;" ::: "memory")

// ---------------------------------------------------------------------------
// smem layout
// ---------------------------------------------------------------------------
#define WS_OFF     0                        // 9 * 8192 = 73728
#define ACT_OFF    73728                    // 4 row slots * 33024
#define SLOT_B     33024                    // 258 px * 128 B
#define BIAS_OFF   (ACT_OFF + 4 * SLOT_B)   // 205824
#define SMEM_BYTES (BIAS_OFF + 256)         // 206080

// ---------------------------------------------------------------------------
// Kernel 1 (proven): per-pixel LN + int8 fake-quant -> fp16 NHWC
// ---------------------------------------------------------------------------
__global__ void __launch_bounds__(128) norm_quant_kernel(const float* __restrict__ x) {
    int p  = blockIdx.x * 128 + threadIdx.x;
    int b  = p >> 16;
    int sp = p & 65535;

    const float* xb = x + (size_t)b * 64 * 65536 + sp;

    float v[64];
    float sum = 0.f;
#pragma unroll
    for (int c = 0; c < 64; c++) { v[c] = xb[(size_t)c << 16]; sum += v[c]; }
    float mu = sum * (1.0f / 64.0f);

    float var = 0.f, mx = 0.f;
#pragma unroll
    for (int c = 0; c < 64; c++) {
        float d = v[c] - mu;
        var += d * d;
        mx = fmaxf(mx, fabsf(d));
    }
    var *= (1.0f / 64.0f);
    float r = rsqrtf(var + 1e-8f);

    float maxn  = fmaxf(mx * r, 1e-8f);
    float s     = 127.0f / maxn;
    float inv_s = maxn * (1.0f / 127.0f);

    __half* yb = g_a + ((size_t)p << 6);
#pragma unroll
    for (int c = 0; c < 64; c += 8) {
        uint4 u;
        __half2 h2;
        float q0, q1;
#define QV(cc) fminf(fmaxf(rintf(s * (r * (v[cc] - mu))), -128.f), 127.f) * inv_s
        q0 = QV(c + 0); q1 = QV(c + 1); h2 = __floats2half2_rn(q0, q1); u.x = *(uint32_t*)&h2;
        q0 = QV(c + 2); q1 = QV(c + 3); h2 = __floats2half2_rn(q0, q1); u.y = *(uint32_t*)&h2;
        q0 = QV(c + 4); q1 = QV(c + 5); h2 = __floats2half2_rn(q0, q1); u.z = *(uint32_t*)&h2;
        q0 = QV(c + 6); q1 = QV(c + 7); h2 = __floats2half2_rn(q0, q1); u.w = *(uint32_t*)&h2;
#undef QV
        *(uint4*)(yb + c) = u;
    }
}

// ---------------------------------------------------------------------------
// Kernel 2 (proven): ternary weight quant -> exact fp16 [tap][co][ci]
// ---------------------------------------------------------------------------
__global__ void __launch_bounds__(512) wq_kernel(const float* __restrict__ Wt) {
    __shared__ float red[16];
    __shared__ float s_w_sh;
    int tid = threadIdx.x;

    float sum = 0.f;
    for (int i = tid; i < 36864; i += 512) sum += fabsf(Wt[i]);
#pragma unroll
    for (int o = 16; o; o >>= 1) sum += __shfl_xor_sync(0xffffffffu, sum, o);
    if ((tid & 31) == 0) red[tid >> 5] = sum;
    __syncthreads();
    if (tid < 32) {
        float s2 = (tid < 16) ? red[tid] : 0.f;
#pragma unroll
        for (int o = 8; o; o >>= 1) s2 += __shfl_xor_sync(0xffffffffu, s2, o);
        if (tid == 0) {
            float mean = s2 * (1.0f / 36864.0f);
            float inv_sw = fmaxf(mean, 1e-8f);
            s_w_sh = 1.0f / inv_sw;
            g_inv_sw = inv_sw;
        }
    }
    __syncthreads();
    float s_w = s_w_sh;

    for (int i = tid; i < 36864; i += 512) {
        float t = rintf(s_w * Wt[i]);
        t = fminf(fmaxf(t, -1.f), 1.f);
        int co  = i / 576;
        int rem = i - co * 576;
        int ci  = rem / 9;
        int tap = rem - ci * 9;
        g_w[(tap * 64 + co) * 64 + ci] = __float2half_rn(t);   // exact
    }
}

// ---------------------------------------------------------------------------
// load one image row r (258 halo'd px x 128B fp16) into ring slot r&3.
// zfill for OOB rows/cols. global byte: ((b<<16 | r<<8 | w) << 7) | c<<4
// smem swizzle (proven): loc*128 + ((c ^ (loc & 7)) << 4)
// ---------------------------------------------------------------------------
__device__ __forceinline__ void load_row(uint32_t sb, int b, int r, int en, int tid) {
    if (!en) return;
    int rc = r < 0 ? 0 : (r > 255 ? 255 : r);
    unsigned rok = ((unsigned)r < 256u) ? 1u : 0u;
    size_t gbase = ((size_t)b << 16) | ((size_t)rc << 8);
    uint32_t slotb = sb + ACT_OFF + (uint32_t)(r & 3) * SLOT_B;
    for (int i = tid; i < 2064; i += 256) {         // 258 px * 8 chunks
        int loc = i >> 3, c = i & 7;
        int w   = loc - 1;
        unsigned ok = rok & (((unsigned)w < 256u) ? 1u : 0u);
        size_t off = ((gbase | (size_t)(ok ? w : 0)) << 7) | ((size_t)c << 4);
        uint32_t dst = slotb + (loc << 7) + ((c ^ (loc & 7)) << 4);
        CP_ASYNC(dst, (const char*)g_a + off, ok ? 16u : 0u);
    }
}

// ---------------------------------------------------------------------------
// Kernel 3: conv. 256 threads, 8 warps; warp w -> out row h+(w&1),
// px [(w>>1)*64, +64) x all 64 co. Strip of row-pairs, 4-slot row ring.
// ---------------------------------------------------------------------------
__global__ void __launch_bounds__(256, 1) conv_kernel(const float* __restrict__ bias,
                                                      float* __restrict__ out) {
    extern __shared__ __align__(1024) unsigned char smem[];
    uint32_t sb = smem_u32(smem);
    int tid = threadIdx.x, wid = tid >> 5, lane = tid & 31;

    int s_ = blockIdx.x;                    // strip 0..18
    int b  = blockIdx.y;                    // image 0..7
    int p0 = (s_ < 14) ? 7 * s_ : 98 + 6 * (s_ - 14);
    int p1 = p0 + ((s_ < 14) ? 7 : 6);      // row-pair range

    // ---- weights -> smem (proven swizzle), bias ----
    for (int i = tid; i < 4608; i += 256) {
        int tap = i >> 9;
        int r   = i & 511;
        int co  = r >> 3;
        int c   = r & 7;
        uint32_t dst = sb + WS_OFF + (tap << 13) + (co << 7) + ((c ^ (co & 7)) << 4);
        CP_ASYNC(dst, (const char*)g_w + ((size_t)i << 4), 16u);
    }
    if (tid < 64) ((float*)(smem + BIAS_OFF))[tid] = bias[tid];

    // ---- prologue: rows 2*p0-1 .. 2*p0+2 into the 4 ring slots ----
    int h0 = 2 * p0;
#pragma unroll
    for (int rr = 0; rr < 4; rr++) load_row(sb, b, h0 - 1 + rr, 1, tid);
    CP_COMMIT();

    float inv_sw = g_inv_sw;

    // ---- per-thread ldmatrix geometry (proven) ----
    int px0    = (wid >> 1) << 6;
    int ho_off = wid & 1;
    int rA   = lane & 15;
    int colA = lane & 16;
    int rB   = lane & 7;
    int colB = ((lane >> 3) & 1) << 4;
    uint32_t rowBterm = (uint32_t)(rB << 7);
    uint32_t cxB = (uint32_t)(colB ^ (rB << 4));
    uint32_t rowbaseA[3], cxA[3];
#pragma unroll
    for (int kw = 0; kw < 3; kw++) {
        rowbaseA[kw] = (uint32_t)((px0 + kw + rA) << 7);
        cxA[kw]      = (uint32_t)(colA ^ (((kw + rA) & 7) << 4));
    }
    int qr = lane >> 2, qc = (lane & 3) << 1;

    float acc[4][8][4];

    auto do_phase = [&](int h, int kh) {
        int in_row = h + ho_off - 1 + kh;
        uint32_t slotb = sb + ACT_OFF + (uint32_t)(in_row & 3) * SLOT_B;
#pragma unroll
        for (int kw = 0; kw < 3; kw++) {
            int tap = kh * 3 + kw;
            uint32_t wb  = sb + WS_OFF + (tap << 13) + rowBterm;
            uint32_t ab  = slotb + rowbaseA[kw];
            uint32_t cxa = cxA[kw];
#pragma unroll
            for (int kk = 0; kk < 4; kk++) {
                uint32_t a[4][4];
#pragma unroll
                for (int mt = 0; mt < 4; mt++)
                    ldsm_x4(a[mt], ab + mt * 2048 + (((uint32_t)kk << 5) ^ cxa));
                uint32_t kB = ((uint32_t)kk << 5) ^ cxB;
#pragma unroll
                for (int n = 0; n < 8; n++) {
                    uint32_t bf[2];
                    ldsm_x2(bf, wb + ((uint32_t)n << 10) + kB);
#pragma unroll
                    for (int mt = 0; mt < 4; mt++)
                        mma16816(acc[mt][n], a[mt], bf);
                }
            }
        }
    };

    for (int p = p0; p < p1; p++) {
        int h  = 2 * p;
        int en = (p + 1 < p1);

        CP_WAIT0();
        __syncthreads();                       // all prefetched rows visible

#pragma unroll
        for (int mt = 0; mt < 4; mt++)
#pragma unroll
            for (int n = 0; n < 8; n++)
#pragma unroll
                for (int e = 0; e < 4; e++) acc[mt][n][e] = 0.f;

        do_phase(h, 0);                        // reads rows h-1 (out h), h (out h+1)
        __syncthreads();                       // row h-1 now dead
        load_row(sb, b, h + 3, en, tid);
        CP_COMMIT();

        do_phase(h, 1);                        // reads rows h, h+1
        __syncthreads();                       // row h now dead
        load_row(sb, b, h + 4, en, tid);
        CP_COMMIT();

        do_phase(h, 2);                        // reads rows h+1, h+2

        // ---- epilogue: weight-scale + bias, fp32 NCHW ----
        const float* bs = (const float*)(smem + BIAS_OFF);
        int ho = h + ho_off;
        float* ob = out + ((size_t)b << 22) + ((size_t)ho << 8);
#pragma unroll
        for (int mt = 0; mt < 4; mt++) {
            int px = px0 + mt * 16 + qr;
#pragma unroll
            for (int n = 0; n < 8; n++) {
                int co = (n << 3) + qc;
                float bc0 = bs[co], bc1 = bs[co + 1];
                float* o0 = ob + ((size_t)co << 16) + px;
                float* o1 = ob + ((size_t)(co + 1) << 16) + px;
                o0[0] = acc[mt][n][0] * inv_sw + bc0;
                o1[0] = acc[mt][n][1] * inv_sw + bc1;
                o0[8] = acc[mt][n][2] * inv_sw + bc0;
                o1[8] = acc[mt][n][3] * inv_sw + bc1;
            }
        }
    }
    CP_WAIT0();
}

// ---------------------------------------------------------------------------
extern "C" void kernel_launch(void* const* d_in, const int* in_sizes, int n_in,
                              void* d_out, int out_size) {
    (void)in_sizes; (void)n_in; (void)out_size;
    const float* x    = (const float*)d_in[0];
    const float* Wt   = (const float*)d_in[1];
    const float* bias = (const float*)d_in[2];
    float* out = (float*)d_out;

    cudaFuncSetAttribute(conv_kernel, cudaFuncAttributeMaxDynamicSharedMemorySize,
                         SMEM_BYTES);

    norm_quant_kernel<<<8 * 65536 / 128, 128>>>(x);
    wq_kernel<<<1, 512>>>(Wt);
    dim3 grid(19, 8);
    conv_kernel<<<grid, 256, SMEM_BYTES>>>(bias, out);
}